// round 9
// baseline (speedup 1.0000x reference)
#include <cuda_runtime.h>
#include <cuda_bf16.h>
#include <cuda_fp16.h>
#include <cstdint>

#define TN 50000
#define TE 800000
#define FIN 256
#define NH 64

// ---------------- device scratch ----------------
__device__ float g_XW[TN * 192];          // fp32 x@W rows (self terms)
__device__ __half2 g_XWH[TN * 96];        // fp16 copy for neighbor messages
__device__ float g_dinv1[3 * TN];
__device__ float g_dinv2[3 * TN];
__device__ int   g_cnt[3 * TN];
__device__ int   g_scan[3 * TN];
__device__ int   g_bsum[256];
__device__ int   g_start[3 * TN];
__device__ int   g_rank[3 * TE];
__device__ int2  g_epack[3 * TE];         // {src, raw ew bits} CSR-grouped by (branch,dst)
__device__ float g_HV[3][TN];             // (h@W2) * dinv2
__device__ uint32_t g_WBH[192 * 128];     // bf16x2 kpair-packed W hi
__device__ uint32_t g_WBL[192 * 128];     // lo part

#define MMA16816(d, a, b) \
    asm volatile("mma.sync.aligned.m16n8k16.row.col.f32.bf16.bf16.f32 " \
                 "{%0,%1,%2,%3},{%4,%5,%6,%7},{%8,%9},{%0,%1,%2,%3};" \
                 : "+f"((d)[0]), "+f"((d)[1]), "+f"((d)[2]), "+f"((d)[3]) \
                 : "r"((a)[0]), "r"((a)[1]), "r"((a)[2]), "r"((a)[3]), \
                   "r"((b)[0]), "r"((b)[1]))

__device__ __forceinline__ uint32_t pack_bf16x2(float x, float y) {
    __nv_bfloat16 hx = __float2bfloat16(x);
    __nv_bfloat16 hy = __float2bfloat16(y);
    return (uint32_t)__bfloat16_as_ushort(hx) |
           ((uint32_t)__bfloat16_as_ushort(hy) << 16);
}

// ---------------- 1a. W bf16-split prep (side stream, feeds GEMM) ----------
__global__ void k_wprep(const float* __restrict__ W1a, const float* __restrict__ W1b,
                        const float* __restrict__ W1c) {
    int i = blockIdx.x * blockDim.x + threadIdx.x;
    if (i >= 192 * 128) return;
    int np = i >> 7;
    int kp = i & 127;
    int v = np >> 6;
    int n = np & 63;
    const float* W = (v == 0) ? W1a : (v == 1) ? W1b : W1c;
    float w0 = W[(2 * kp) * NH + n];
    float w1 = W[(2 * kp + 1) * NH + n];
    __nv_bfloat16 h0 = __float2bfloat16(w0);
    __nv_bfloat16 h1 = __float2bfloat16(w1);
    g_WBH[np * 128 + kp] = (uint32_t)__bfloat16_as_ushort(h0) |
                           ((uint32_t)__bfloat16_as_ushort(h1) << 16);
    g_WBL[np * 128 + kp] = pack_bf16x2(w0 - __bfloat162float(h0),
                                       w1 - __bfloat162float(h1));
}

// ---------------- 1b. degree init (main stream) ----------------
__global__ void k_initdeg() {
    int i = blockIdx.x * blockDim.x + threadIdx.x;
    if (i < 3 * TN) {
        g_dinv1[i] = 1.0f;   // self-loop weight
        g_cnt[i] = 0;
    }
}

// ---------------- 2. degree scatter + rank ----------------
__global__ void k_deg(const int* __restrict__ ei0, const int* __restrict__ ei1,
                      const int* __restrict__ ei2,
                      const float* __restrict__ ew0, const float* __restrict__ ew1,
                      const float* __restrict__ ew2) {
    int t = blockIdx.x * blockDim.x + threadIdx.x;
    if (t >= 3 * TE) return;
    int b = t / TE;
    int e = t - b * TE;
    const int* ei = (b == 0) ? ei0 : (b == 1) ? ei1 : ei2;
    const float* ew = (b == 0) ? ew0 : (b == 1) ? ew1 : ew2;
    int dst = ei[TE + e];
    g_rank[t] = atomicAdd(&g_cnt[b * TN + dst], 1);
    atomicAdd(&g_dinv1[b * TN + dst], ew[e]);
}

// ---------------- 3. scan ----------------
__global__ void k_scan1() {
    __shared__ int sh[1024];
    int t = threadIdx.x;
    int i = blockIdx.x * 1024 + t;
    int v = (i < 3 * TN) ? g_cnt[i] : 0;
    sh[t] = v;
    for (int off = 1; off < 1024; off <<= 1) {
        __syncthreads();
        int a = (t >= off) ? sh[t - off] : 0;
        __syncthreads();
        sh[t] += a;
    }
    __syncthreads();
    if (i < 3 * TN) g_scan[i] = sh[t] - v;
    if (t == 1023) g_bsum[blockIdx.x] = sh[1023];
}
__global__ void k_scan2(int nb) {
    __shared__ int sh[256];
    int t = threadIdx.x;
    int v = (t < nb) ? g_bsum[t] : 0;
    sh[t] = v;
    for (int off = 1; off < 256; off <<= 1) {
        __syncthreads();
        int a = (t >= off) ? sh[t - off] : 0;
        __syncthreads();
        sh[t] += a;
    }
    __syncthreads();
    g_bsum[t] = sh[t] - v;
}
__global__ void k_scan3() {   // + rsqrt fused
    int i = blockIdx.x * blockDim.x + threadIdx.x;
    if (i >= 3 * TN) return;
    g_start[i] = g_scan[i] + g_bsum[i >> 10];
    g_dinv2[i] = rsqrtf((float)g_cnt[i] + 1.0f);
    g_dinv1[i] = rsqrtf(g_dinv1[i]);
}

// ---------------- 4. tensor-core GEMM via mma.sync (bf16 hi/lo split) ----------
#define GEMM_SMEM 73728
__global__ void __launch_bounds__(256, 2) k_gemm_mma(const float* __restrict__ x) {
    extern __shared__ uint32_t sm[];
    uint32_t* sAh = sm;                  // [64][36]
    uint32_t* sAl = sm + 64 * 36;
    uint32_t* sBh = sm + 2 * 64 * 36;    // [192][36]
    uint32_t* sBl = sm + 2 * 64 * 36 + 192 * 36;

    int tid = threadIdx.x;
    int wid = tid >> 5, lane = tid & 31;
    int wm = wid >> 2, wn = wid & 3;
    int row0 = blockIdx.x * 64;
    int lr = lane >> 2;
    int lk = lane & 3;

    float d[2][6][4];
#pragma unroll
    for (int a = 0; a < 2; a++)
#pragma unroll
        for (int b = 0; b < 6; b++)
#pragma unroll
            for (int c = 0; c < 4; c++) d[a][b][c] = 0.f;

    const float2* x2 = (const float2*)x;
    for (int c = 0; c < 4; c++) {
#pragma unroll
        for (int it = 0; it < 8; it++) {
            int idx = tid + it * 256;
            int r = idx >> 5, kp = idx & 31;
            int gr = row0 + r;
            float2 v = (gr < TN) ? x2[gr * 128 + c * 32 + kp] : make_float2(0.f, 0.f);
            __nv_bfloat16 h0 = __float2bfloat16(v.x);
            __nv_bfloat16 h1 = __float2bfloat16(v.y);
            sAh[r * 36 + kp] = (uint32_t)__bfloat16_as_ushort(h0) |
                               ((uint32_t)__bfloat16_as_ushort(h1) << 16);
            sAl[r * 36 + kp] = pack_bf16x2(v.x - __bfloat162float(h0),
                                           v.y - __bfloat162float(h1));
        }
#pragma unroll
        for (int it = 0; it < 24; it++) {
            int idx = tid + it * 256;
            int n = idx >> 5, kp = idx & 31;
            sBh[n * 36 + kp] = g_WBH[n * 128 + c * 32 + kp];
            sBl[n * 36 + kp] = g_WBL[n * 128 + c * 32 + kp];
        }
        __syncthreads();
#pragma unroll
        for (int ks = 0; ks < 4; ks++) {
            int kw = ks * 8 + lk;
            uint32_t ah[2][4], al[2][4], bh[6][2], bl[6][2];
#pragma unroll
            for (int f = 0; f < 2; f++) {
                int r = wm * 32 + f * 16 + lr;
                ah[f][0] = sAh[r * 36 + kw];
                ah[f][1] = sAh[(r + 8) * 36 + kw];
                ah[f][2] = sAh[r * 36 + kw + 4];
                ah[f][3] = sAh[(r + 8) * 36 + kw + 4];
                al[f][0] = sAl[r * 36 + kw];
                al[f][1] = sAl[(r + 8) * 36 + kw];
                al[f][2] = sAl[r * 36 + kw + 4];
                al[f][3] = sAl[(r + 8) * 36 + kw + 4];
            }
#pragma unroll
            for (int f = 0; f < 6; f++) {
                int n = wn * 48 + f * 8 + lr;
                bh[f][0] = sBh[n * 36 + kw];
                bh[f][1] = sBh[n * 36 + kw + 4];
                bl[f][0] = sBl[n * 36 + kw];
                bl[f][1] = sBl[n * 36 + kw + 4];
            }
#pragma unroll
            for (int fm = 0; fm < 2; fm++)
#pragma unroll
                for (int fn = 0; fn < 6; fn++) {
                    MMA16816(d[fm][fn], ah[fm], bh[fn]);
                    MMA16816(d[fm][fn], al[fm], bh[fn]);
                    MMA16816(d[fm][fn], ah[fm], bl[fn]);
                }
        }
        __syncthreads();
    }
#pragma unroll
    for (int fm = 0; fm < 2; fm++) {
        int gr = row0 + wm * 32 + fm * 16 + lr;
#pragma unroll
        for (int fn = 0; fn < 6; fn++) {
            int col = wn * 48 + fn * 8 + lk * 2;
            if (gr < TN) {
                *(float2*)&g_XW[gr * 192 + col] = make_float2(d[fm][fn][0], d[fm][fn][1]);
                g_XWH[gr * 96 + (col >> 1)] = __floats2half2_rn(d[fm][fn][0], d[fm][fn][1]);
            }
            if (gr + 8 < TN) {
                *(float2*)&g_XW[(gr + 8) * 192 + col] = make_float2(d[fm][fn][2], d[fm][fn][3]);
                g_XWH[(gr + 8) * 96 + (col >> 1)] = __floats2half2_rn(d[fm][fn][2], d[fm][fn][3]);
            }
        }
    }
}

// ---------------- 5. CSR scatter (no random loads) ----------------
__global__ void k_scatter(const int* __restrict__ ei0, const int* __restrict__ ei1,
                          const int* __restrict__ ei2,
                          const float* __restrict__ ew0, const float* __restrict__ ew1,
                          const float* __restrict__ ew2) {
    int t = blockIdx.x * blockDim.x + threadIdx.x;
    if (t >= 3 * TE) return;
    int b = t / TE;
    int e = t - b * TE;
    const int* ei = (b == 0) ? ei0 : (b == 1) ? ei1 : ei2;
    const float* ew = (b == 0) ? ew0 : (b == 1) ? ew1 : ew2;
    int src = ei[e];
    int dst = ei[TE + e];
    int pos = g_start[b * TN + dst] + g_rank[t];
    g_epack[pos] = make_int2(src, __float_as_int(ew[e]));
}

// ---------------- 6. fused conv1 gather (fp16 messages, MLP-4) ----------------
__global__ void k_gather(const float* __restrict__ b1a, const float* __restrict__ b1b,
                         const float* __restrict__ b1c,
                         const float* __restrict__ W2a, const float* __restrict__ W2b,
                         const float* __restrict__ W2c,
                         float* __restrict__ out) {
    int warp = (blockIdx.x * blockDim.x + threadIdx.x) >> 5;
    int lane = threadIdx.x & 31;
    if (warp >= TN) return;
    int i = warp;
    float f0 = 0.f, f1 = 0.f;
#pragma unroll
    for (int b = 0; b < 3; b++) {
        const float* b1 = (b == 0) ? b1a : (b == 1) ? b1b : b1c;
        const float* W2 = (b == 0) ? W2a : (b == 1) ? W2b : W2c;
        const float* dv1 = g_dinv1 + b * TN;
        float dv = dv1[i];
        float2 xwi = ((const float2*)(g_XW + i * 192 + b * 64))[lane];
        float2 bb = ((const float2*)b1)[lane];
        int s = g_start[b * TN + i];
        int c = g_cnt[b * TN + i];
        int boff = b * 32 + lane;
        float e0a = 0.f, e1a = 0.f;     // edge accumulators (no dv factor)
        int j = 0;
#pragma unroll 1
        for (; j + 4 <= c; j += 4) {
            int2 p0 = g_epack[s + j];
            int2 p1 = g_epack[s + j + 1];
            int2 p2 = g_epack[s + j + 2];
            int2 p3 = g_epack[s + j + 3];
            float d0 = dv1[p0.x], d1 = dv1[p1.x], d2 = dv1[p2.x], d3 = dv1[p3.x];
            float2 m0 = __half22float2(g_XWH[p0.x * 96 + boff]);
            float2 m1 = __half22float2(g_XWH[p1.x * 96 + boff]);
            float2 m2 = __half22float2(g_XWH[p2.x * 96 + boff]);
            float2 m3 = __half22float2(g_XWH[p3.x * 96 + boff]);
            float n0 = __int_as_float(p0.y) * d0;
            float n1 = __int_as_float(p1.y) * d1;
            float n2 = __int_as_float(p2.y) * d2;
            float n3 = __int_as_float(p3.y) * d3;
            e0a = fmaf(m0.x, n0, e0a); e1a = fmaf(m0.y, n0, e1a);
            e0a = fmaf(m1.x, n1, e0a); e1a = fmaf(m1.y, n1, e1a);
            e0a = fmaf(m2.x, n2, e0a); e1a = fmaf(m2.y, n2, e1a);
            e0a = fmaf(m3.x, n3, e0a); e1a = fmaf(m3.y, n3, e1a);
        }
#pragma unroll 1
        for (; j < c; j++) {
            int2 p = g_epack[s + j];
            float nm = __int_as_float(p.y) * dv1[p.x];
            float2 m = __half22float2(g_XWH[p.x * 96 + boff]);
            e0a = fmaf(m.x, nm, e0a);
            e1a = fmaf(m.y, nm, e1a);
        }
        float a0 = fmaf(dv, e0a, bb.x + xwi.x * dv * dv);
        float a1 = fmaf(dv, e1a, bb.y + xwi.y * dv * dv);
        float h0 = fmaxf(a0, 0.f);
        float h1 = fmaxf(a1, 0.f);
        f0 += h0;
        f1 += h1;
        float2 w2 = ((const float2*)W2)[lane];
        float dot = h0 * w2.x + h1 * w2.y;
#pragma unroll
        for (int o = 16; o; o >>= 1) dot += __shfl_xor_sync(0xFFFFFFFFu, dot, o);
        if (lane == 0) g_HV[b][i] = dot * g_dinv2[b * TN + i];
    }
    ((float2*)(out + TN + (long)i * NH))[lane] = make_float2(f0, f1);
}

// ---------------- 7. conv2 gather (warp per node) + final sum ----------------
__global__ void k_conv2(const float* __restrict__ b2a, const float* __restrict__ b2b,
                        const float* __restrict__ b2c, float* __restrict__ out) {
    int warp = (blockIdx.x * blockDim.x + threadIdx.x) >> 5;
    int lane = threadIdx.x & 31;
    if (warp >= TN) return;
    int i = warp;
    float r = 0.f;
#pragma unroll
    for (int b = 0; b < 3; b++) {
        const float* b2 = (b == 0) ? b2a : (b == 1) ? b2b : b2c;
        int s = g_start[b * TN + i];
        int c = g_cnt[b * TN + i];
        float acc = 0.f;
        for (int j = lane; j < c; j += 32)
            acc += g_HV[b][g_epack[s + j].x];
#pragma unroll
        for (int o = 16; o; o >>= 1) acc += __shfl_xor_sync(0xFFFFFFFFu, acc, o);
        r += b2[0] + g_dinv2[b * TN + i] * (g_HV[b][i] + acc);
    }
    if (lane == 0) out[i] = r;
}

extern "C" void kernel_launch(void* const* d_in, const int* in_sizes, int n_in,
                              void* d_out, int out_size) {
    const float* x   = (const float*)d_in[0];
    const int*   ei0 = (const int*)d_in[1];
    const int*   ei1 = (const int*)d_in[2];
    const int*   ei2 = (const int*)d_in[3];
    const float* ew0 = (const float*)d_in[4];
    const float* ew1 = (const float*)d_in[5];
    const float* ew2 = (const float*)d_in[6];
    const float* W1a = (const float*)d_in[7];
    const float* b1a = (const float*)d_in[8];
    const float* W2a = (const float*)d_in[9];
    const float* b2a = (const float*)d_in[10];
    const float* W1b = (const float*)d_in[11];
    const float* b1b = (const float*)d_in[12];
    const float* W2b = (const float*)d_in[13];
    const float* b2b = (const float*)d_in[14];
    const float* W1c = (const float*)d_in[15];
    const float* b1c = (const float*)d_in[16];
    const float* W2c = (const float*)d_in[17];
    const float* b2c = (const float*)d_in[18];
    float* out = (float*)d_out;

    static cudaStream_t s1 = nullptr;
    static cudaEvent_t evFork = nullptr, evJoin = nullptr;
    if (!s1) {
        cudaStreamCreateWithFlags(&s1, cudaStreamNonBlocking);
        cudaEventCreateWithFlags(&evFork, cudaEventDisableTiming);
        cudaEventCreateWithFlags(&evJoin, cudaEventDisableTiming);
        cudaFuncSetAttribute(k_gemm_mma, cudaFuncAttributeMaxDynamicSharedMemorySize,
                             GEMM_SMEM);
    }

    int nb = (3 * TN + 1023) / 1024;

    // fork: W-prep + GEMM on side stream; edge pipeline on main stream
    cudaEventRecord(evFork, 0);
    cudaStreamWaitEvent(s1, evFork, 0);
    k_wprep<<<(192 * 128 + 255) / 256, 256, 0, s1>>>(W1a, W1b, W1c);
    k_gemm_mma<<<(TN + 63) / 64, 256, GEMM_SMEM, s1>>>(x);
    cudaEventRecord(evJoin, s1);

    k_initdeg<<<(3 * TN + 255) / 256, 256>>>();
    k_deg<<<(3 * TE + 255) / 256, 256>>>(ei0, ei1, ei2, ew0, ew1, ew2);
    k_scan1<<<nb, 1024>>>();
    k_scan2<<<1, 256>>>(nb);
    k_scan3<<<(3 * TN + 255) / 256, 256>>>();
    k_scatter<<<(3 * TE + 255) / 256, 256>>>(ei0, ei1, ei2, ew0, ew1, ew2);

    // join before gather (needs XW/XWH)
    cudaStreamWaitEvent(0, evJoin, 0);
    k_gather<<<(TN * 32 + 255) / 256, 256>>>(b1a, b1b, b1c, W2a, W2b, W2c, out);
    k_conv2<<<(TN * 32 + 255) / 256, 256>>>(b2a, b2b, b2c, out);
}

// round 10
// speedup vs baseline: 1.0668x; 1.0668x over previous
#include <cuda_runtime.h>
#include <cuda_bf16.h>
#include <cuda_fp16.h>
#include <cstdint>

#define TN 50000
#define TE 800000
#define FIN 256
#define NH 64

typedef unsigned long long ull;

// ---------------- device scratch ----------------
__device__ float g_XW[TN * 192];          // fp32 x@W rows (self terms)
__device__ __half2 g_XWH[TN * 96];        // fp16 copy for neighbor messages
__device__ ull   g_pack[3 * TN];          // count<<42 | sum(w*2^24)
__device__ float g_dinv1[3 * TN];
__device__ float g_dinv2[3 * TN];
__device__ int   g_cnt[3 * TN];
__device__ int   g_scan[3 * TN];
__device__ int   g_bsum[256];
__device__ int   g_start[3 * TN];
__device__ int   g_rank[3 * TE];
__device__ int2  g_epack[3 * TE];         // {src, norm-bits} CSR-grouped by (branch,dst)
__device__ float g_HV[3][TN];             // (h@W2) * dinv2
__device__ uint32_t g_WBH[192 * 128];     // bf16x2 kpair-packed W hi
__device__ uint32_t g_WBL[192 * 128];     // lo part

#define MMA16816(d, a, b) \
    asm volatile("mma.sync.aligned.m16n8k16.row.col.f32.bf16.bf16.f32 " \
                 "{%0,%1,%2,%3},{%4,%5,%6,%7},{%8,%9},{%0,%1,%2,%3};" \
                 : "+f"((d)[0]), "+f"((d)[1]), "+f"((d)[2]), "+f"((d)[3]) \
                 : "r"((a)[0]), "r"((a)[1]), "r"((a)[2]), "r"((a)[3]), \
                   "r"((b)[0]), "r"((b)[1]))

__device__ __forceinline__ uint32_t pack_bf16x2(float x, float y) {
    __nv_bfloat16 hx = __float2bfloat16(x);
    __nv_bfloat16 hy = __float2bfloat16(y);
    return (uint32_t)__bfloat16_as_ushort(hx) |
           ((uint32_t)__bfloat16_as_ushort(hy) << 16);
}

// ---------------- 1a. W bf16-split prep (side stream, feeds GEMM) ----------
__global__ void k_wprep(const float* __restrict__ W1a, const float* __restrict__ W1b,
                        const float* __restrict__ W1c) {
    int i = blockIdx.x * blockDim.x + threadIdx.x;
    if (i >= 192 * 128) return;
    int np = i >> 7;
    int kp = i & 127;
    int v = np >> 6;
    int n = np & 63;
    const float* W = (v == 0) ? W1a : (v == 1) ? W1b : W1c;
    float w0 = W[(2 * kp) * NH + n];
    float w1 = W[(2 * kp + 1) * NH + n];
    __nv_bfloat16 h0 = __float2bfloat16(w0);
    __nv_bfloat16 h1 = __float2bfloat16(w1);
    g_WBH[np * 128 + kp] = (uint32_t)__bfloat16_as_ushort(h0) |
                           ((uint32_t)__bfloat16_as_ushort(h1) << 16);
    g_WBL[np * 128 + kp] = pack_bf16x2(w0 - __bfloat162float(h0),
                                       w1 - __bfloat162float(h1));
}

// ---------------- 1b. degree init ----------------
__global__ void k_initdeg() {
    int i = blockIdx.x * blockDim.x + threadIdx.x;
    if (i < 3 * TN) g_pack[i] = 0ull;
}

// ---------------- 2. packed degree scatter + rank (2 edges/thread) --------
__global__ void k_deg(const int* __restrict__ ei0, const int* __restrict__ ei1,
                      const int* __restrict__ ei2,
                      const float* __restrict__ ew0, const float* __restrict__ ew1,
                      const float* __restrict__ ew2) {
    int t = blockIdx.x * blockDim.x + threadIdx.x;
    if (t >= 3 * (TE / 2)) return;
    int b = t / (TE / 2);
    int e = (t - b * (TE / 2)) * 2;
    const int* ei = (b == 0) ? ei0 : (b == 1) ? ei1 : ei2;
    const float* ew = (b == 0) ? ew0 : (b == 1) ? ew1 : ew2;
    int2 dst2 = *(const int2*)&ei[TE + e];
    float2 w2 = *(const float2*)&ew[e];
    ull* packb = g_pack + b * TN;
    ull o0 = atomicAdd(&packb[dst2.x],
                       (1ull << 42) | (ull)__float2uint_rn(w2.x * 16777216.f));
    ull o1 = atomicAdd(&packb[dst2.y],
                       (1ull << 42) | (ull)__float2uint_rn(w2.y * 16777216.f));
    *(int2*)&g_rank[b * TE + e] = make_int2((int)(o0 >> 42), (int)(o1 >> 42));
}

// ---------------- 3. scan ----------------
__global__ void k_scan1() {
    __shared__ int sh[1024];
    int t = threadIdx.x;
    int i = blockIdx.x * 1024 + t;
    int v = (i < 3 * TN) ? (int)(g_pack[i] >> 42) : 0;
    sh[t] = v;
    for (int off = 1; off < 1024; off <<= 1) {
        __syncthreads();
        int a = (t >= off) ? sh[t - off] : 0;
        __syncthreads();
        sh[t] += a;
    }
    __syncthreads();
    if (i < 3 * TN) g_scan[i] = sh[t] - v;
    if (t == 1023) g_bsum[blockIdx.x] = sh[1023];
}
__global__ void k_scan2(int nb) {
    __shared__ int sh[256];
    int t = threadIdx.x;
    int v = (t < nb) ? g_bsum[t] : 0;
    sh[t] = v;
    for (int off = 1; off < 256; off <<= 1) {
        __syncthreads();
        int a = (t >= off) ? sh[t - off] : 0;
        __syncthreads();
        sh[t] += a;
    }
    __syncthreads();
    g_bsum[t] = sh[t] - v;
}
__global__ void k_scan3() {   // unpack + rsqrt fused
    int i = blockIdx.x * blockDim.x + threadIdx.x;
    if (i >= 3 * TN) return;
    ull p = g_pack[i];
    int cnt = (int)(p >> 42);
    float wsum = (float)(p & ((1ull << 42) - 1)) * (1.0f / 16777216.0f);
    g_cnt[i] = cnt;
    g_start[i] = g_scan[i] + g_bsum[i >> 10];
    g_dinv1[i] = rsqrtf(1.0f + wsum);
    g_dinv2[i] = rsqrtf((float)cnt + 1.0f);
}

// ---------------- 4. tensor-core GEMM via mma.sync (bf16 hi/lo split) ----------
#define GEMM_SMEM 73728
__global__ void __launch_bounds__(256, 2) k_gemm_mma(const float* __restrict__ x) {
    extern __shared__ uint32_t sm[];
    uint32_t* sAh = sm;                  // [64][36]
    uint32_t* sAl = sm + 64 * 36;
    uint32_t* sBh = sm + 2 * 64 * 36;    // [192][36]
    uint32_t* sBl = sm + 2 * 64 * 36 + 192 * 36;

    int tid = threadIdx.x;
    int wid = tid >> 5, lane = tid & 31;
    int wm = wid >> 2, wn = wid & 3;
    int row0 = blockIdx.x * 64;
    int lr = lane >> 2;
    int lk = lane & 3;

    float d[2][6][4];
#pragma unroll
    for (int a = 0; a < 2; a++)
#pragma unroll
        for (int b = 0; b < 6; b++)
#pragma unroll
            for (int c = 0; c < 4; c++) d[a][b][c] = 0.f;

    const float2* x2 = (const float2*)x;
    for (int c = 0; c < 4; c++) {
#pragma unroll
        for (int it = 0; it < 8; it++) {
            int idx = tid + it * 256;
            int r = idx >> 5, kp = idx & 31;
            int gr = row0 + r;
            float2 v = (gr < TN) ? x2[gr * 128 + c * 32 + kp] : make_float2(0.f, 0.f);
            __nv_bfloat16 h0 = __float2bfloat16(v.x);
            __nv_bfloat16 h1 = __float2bfloat16(v.y);
            sAh[r * 36 + kp] = (uint32_t)__bfloat16_as_ushort(h0) |
                               ((uint32_t)__bfloat16_as_ushort(h1) << 16);
            sAl[r * 36 + kp] = pack_bf16x2(v.x - __bfloat162float(h0),
                                           v.y - __bfloat162float(h1));
        }
#pragma unroll
        for (int it = 0; it < 24; it++) {
            int idx = tid + it * 256;
            int n = idx >> 5, kp = idx & 31;
            sBh[n * 36 + kp] = g_WBH[n * 128 + c * 32 + kp];
            sBl[n * 36 + kp] = g_WBL[n * 128 + c * 32 + kp];
        }
        __syncthreads();
#pragma unroll
        for (int ks = 0; ks < 4; ks++) {
            int kw = ks * 8 + lk;
            uint32_t ah[2][4], al[2][4], bh[6][2], bl[6][2];
#pragma unroll
            for (int f = 0; f < 2; f++) {
                int r = wm * 32 + f * 16 + lr;
                ah[f][0] = sAh[r * 36 + kw];
                ah[f][1] = sAh[(r + 8) * 36 + kw];
                ah[f][2] = sAh[r * 36 + kw + 4];
                ah[f][3] = sAh[(r + 8) * 36 + kw + 4];
                al[f][0] = sAl[r * 36 + kw];
                al[f][1] = sAl[(r + 8) * 36 + kw];
                al[f][2] = sAl[r * 36 + kw + 4];
                al[f][3] = sAl[(r + 8) * 36 + kw + 4];
            }
#pragma unroll
            for (int f = 0; f < 6; f++) {
                int n = wn * 48 + f * 8 + lr;
                bh[f][0] = sBh[n * 36 + kw];
                bh[f][1] = sBh[n * 36 + kw + 4];
                bl[f][0] = sBl[n * 36 + kw];
                bl[f][1] = sBl[n * 36 + kw + 4];
            }
#pragma unroll
            for (int fm = 0; fm < 2; fm++)
#pragma unroll
                for (int fn = 0; fn < 6; fn++) {
                    MMA16816(d[fm][fn], ah[fm], bh[fn]);
                    MMA16816(d[fm][fn], al[fm], bh[fn]);
                    MMA16816(d[fm][fn], ah[fm], bl[fn]);
                }
        }
        __syncthreads();
    }
#pragma unroll
    for (int fm = 0; fm < 2; fm++) {
        int gr = row0 + wm * 32 + fm * 16 + lr;
#pragma unroll
        for (int fn = 0; fn < 6; fn++) {
            int col = wn * 48 + fn * 8 + lk * 2;
            if (gr < TN) {
                *(float2*)&g_XW[gr * 192 + col] = make_float2(d[fm][fn][0], d[fm][fn][1]);
                g_XWH[gr * 96 + (col >> 1)] = __floats2half2_rn(d[fm][fn][0], d[fm][fn][1]);
            }
            if (gr + 8 < TN) {
                *(float2*)&g_XW[(gr + 8) * 192 + col] = make_float2(d[fm][fn][2], d[fm][fn][3]);
                g_XWH[(gr + 8) * 96 + (col >> 1)] = __floats2half2_rn(d[fm][fn][2], d[fm][fn][3]);
            }
        }
    }
}

// ---------------- 5. CSR scatter (norm precomputed here) ----------------
__global__ void k_scatter(const int* __restrict__ ei0, const int* __restrict__ ei1,
                          const int* __restrict__ ei2,
                          const float* __restrict__ ew0, const float* __restrict__ ew1,
                          const float* __restrict__ ew2) {
    int t = blockIdx.x * blockDim.x + threadIdx.x;
    if (t >= 3 * TE) return;
    int b = t / TE;
    int e = t - b * TE;
    const int* ei = (b == 0) ? ei0 : (b == 1) ? ei1 : ei2;
    const float* ew = (b == 0) ? ew0 : (b == 1) ? ew1 : ew2;
    int src = ei[e];
    int dst = ei[TE + e];
    float norm = g_dinv1[b * TN + src] * ew[e] * g_dinv1[b * TN + dst];
    int pos = g_start[b * TN + dst] + g_rank[t];
    g_epack[pos] = make_int2(src, __float_as_int(norm));
}

// ---------------- 6. fused conv1 gather (fp16 messages, MLP-4) ----------------
__global__ void k_gather(const float* __restrict__ b1a, const float* __restrict__ b1b,
                         const float* __restrict__ b1c,
                         const float* __restrict__ W2a, const float* __restrict__ W2b,
                         const float* __restrict__ W2c,
                         float* __restrict__ out) {
    int warp = (blockIdx.x * blockDim.x + threadIdx.x) >> 5;
    int lane = threadIdx.x & 31;
    if (warp >= TN) return;
    int i = warp;
    float f0 = 0.f, f1 = 0.f;
#pragma unroll
    for (int b = 0; b < 3; b++) {
        const float* b1 = (b == 0) ? b1a : (b == 1) ? b1b : b1c;
        const float* W2 = (b == 0) ? W2a : (b == 1) ? W2b : W2c;
        float dgi = g_dinv1[b * TN + i];
        float2 xwi = ((const float2*)(g_XW + i * 192 + b * 64))[lane];
        float2 bb = ((const float2*)b1)[lane];
        float a0 = bb.x + xwi.x * dgi * dgi;
        float a1 = bb.y + xwi.y * dgi * dgi;
        int s = g_start[b * TN + i];
        int c = g_cnt[b * TN + i];
        int boff = b * 32 + lane;
        int j = 0;
#pragma unroll 1
        for (; j + 4 <= c; j += 4) {
            int2 p0 = g_epack[s + j];
            int2 p1 = g_epack[s + j + 1];
            int2 p2 = g_epack[s + j + 2];
            int2 p3 = g_epack[s + j + 3];
            float2 m0 = __half22float2(g_XWH[p0.x * 96 + boff]);
            float2 m1 = __half22float2(g_XWH[p1.x * 96 + boff]);
            float2 m2 = __half22float2(g_XWH[p2.x * 96 + boff]);
            float2 m3 = __half22float2(g_XWH[p3.x * 96 + boff]);
            float n0 = __int_as_float(p0.y), n1 = __int_as_float(p1.y);
            float n2 = __int_as_float(p2.y), n3 = __int_as_float(p3.y);
            a0 = fmaf(m0.x, n0, a0); a1 = fmaf(m0.y, n0, a1);
            a0 = fmaf(m1.x, n1, a0); a1 = fmaf(m1.y, n1, a1);
            a0 = fmaf(m2.x, n2, a0); a1 = fmaf(m2.y, n2, a1);
            a0 = fmaf(m3.x, n3, a0); a1 = fmaf(m3.y, n3, a1);
        }
#pragma unroll 1
        for (; j < c; j++) {
            int2 p = g_epack[s + j];
            float nm = __int_as_float(p.y);
            float2 m = __half22float2(g_XWH[p.x * 96 + boff]);
            a0 = fmaf(m.x, nm, a0);
            a1 = fmaf(m.y, nm, a1);
        }
        float h0 = fmaxf(a0, 0.f);
        float h1 = fmaxf(a1, 0.f);
        f0 += h0;
        f1 += h1;
        float2 w2 = ((const float2*)W2)[lane];
        float dot = h0 * w2.x + h1 * w2.y;
#pragma unroll
        for (int o = 16; o; o >>= 1) dot += __shfl_xor_sync(0xFFFFFFFFu, dot, o);
        if (lane == 0) g_HV[b][i] = dot * g_dinv2[b * TN + i];
    }
    ((float2*)(out + TN + (long)i * NH))[lane] = make_float2(f0, f1);
}

// ---------------- 7. conv2 gather (warp per node) + final sum ----------------
__global__ void k_conv2(const float* __restrict__ b2a, const float* __restrict__ b2b,
                        const float* __restrict__ b2c, float* __restrict__ out) {
    int warp = (blockIdx.x * blockDim.x + threadIdx.x) >> 5;
    int lane = threadIdx.x & 31;
    if (warp >= TN) return;
    int i = warp;
    float r = 0.f;
#pragma unroll
    for (int b = 0; b < 3; b++) {
        const float* b2 = (b == 0) ? b2a : (b == 1) ? b2b : b2c;
        int s = g_start[b * TN + i];
        int c = g_cnt[b * TN + i];
        float acc = 0.f;
        for (int j = lane; j < c; j += 32)
            acc += g_HV[b][g_epack[s + j].x];
#pragma unroll
        for (int o = 16; o; o >>= 1) acc += __shfl_xor_sync(0xFFFFFFFFu, acc, o);
        r += b2[0] + g_dinv2[b * TN + i] * (g_HV[b][i] + acc);
    }
    if (lane == 0) out[i] = r;
}

extern "C" void kernel_launch(void* const* d_in, const int* in_sizes, int n_in,
                              void* d_out, int out_size) {
    const float* x   = (const float*)d_in[0];
    const int*   ei0 = (const int*)d_in[1];
    const int*   ei1 = (const int*)d_in[2];
    const int*   ei2 = (const int*)d_in[3];
    const float* ew0 = (const float*)d_in[4];
    const float* ew1 = (const float*)d_in[5];
    const float* ew2 = (const float*)d_in[6];
    const float* W1a = (const float*)d_in[7];
    const float* b1a = (const float*)d_in[8];
    const float* W2a = (const float*)d_in[9];
    const float* b2a = (const float*)d_in[10];
    const float* W1b = (const float*)d_in[11];
    const float* b1b = (const float*)d_in[12];
    const float* W2b = (const float*)d_in[13];
    const float* b2b = (const float*)d_in[14];
    const float* W1c = (const float*)d_in[15];
    const float* b1c = (const float*)d_in[16];
    const float* W2c = (const float*)d_in[17];
    const float* b2c = (const float*)d_in[18];
    float* out = (float*)d_out;

    static cudaStream_t s1 = nullptr;
    static cudaEvent_t evFork = nullptr, evJoin = nullptr;
    if (!s1) {
        cudaStreamCreateWithFlags(&s1, cudaStreamNonBlocking);
        cudaEventCreateWithFlags(&evFork, cudaEventDisableTiming);
        cudaEventCreateWithFlags(&evJoin, cudaEventDisableTiming);
        cudaFuncSetAttribute(k_gemm_mma, cudaFuncAttributeMaxDynamicSharedMemorySize,
                             GEMM_SMEM);
    }

    int nb = (3 * TN + 1023) / 1024;

    // fork: W-prep + GEMM on side stream; edge pipeline on main stream
    cudaEventRecord(evFork, 0);
    cudaStreamWaitEvent(s1, evFork, 0);
    k_wprep<<<(192 * 128 + 255) / 256, 256, 0, s1>>>(W1a, W1b, W1c);
    k_gemm_mma<<<(TN + 63) / 64, 256, GEMM_SMEM, s1>>>(x);
    cudaEventRecord(evJoin, s1);

    k_initdeg<<<(3 * TN + 255) / 256, 256>>>();
    k_deg<<<(3 * (TE / 2) + 255) / 256, 256>>>(ei0, ei1, ei2, ew0, ew1, ew2);
    k_scan1<<<nb, 1024>>>();
    k_scan2<<<1, 256>>>(nb);
    k_scan3<<<(3 * TN + 255) / 256, 256>>>();
    k_scatter<<<(3 * TE + 255) / 256, 256>>>(ei0, ei1, ei2, ew0, ew1, ew2);

    // join before gather (needs XW/XWH)
    cudaStreamWaitEvent(0, evJoin, 0);
    k_gather<<<(TN * 32 + 255) / 256, 256>>>(b1a, b1b, b1c, W2a, W2b, W2c, out);
    k_conv2<<<(TN * 32 + 255) / 256, 256>>>(b2a, b2b, b2c, out);
}